// round 11
// baseline (speedup 1.0000x reference)
#include <cuda_runtime.h>
#include <cstdint>

#define BB 2
#define DD 512
#define KK 32
#define NN 4096
#define GRID 256
#define NTHR 512
#define ZSIZE (BB*DD*KK)

typedef unsigned long long ull;

// ---------- device scratch ----------
__device__ float2 g_ABi[DD*KK];              // (s^2, -2 s^2 c) interleaved, 128KB
__device__ float g_C[KK];
__device__ float g_S1part[GRID*KK];
__device__ float g_M2[(size_t)BB*128*DD*KK]; // [b*128+chunk][d][k] 16MB
__device__ float g_SS[BB*128*KK];
__device__ unsigned g_sync[3];               // rotating counters (zero-init)

// ---------- f32x2 helpers ----------
__device__ __forceinline__ ull pk2(float lo, float hi) {
    ull r; asm("mov.b64 %0, {%1,%2};" : "=l"(r) : "f"(lo), "f"(hi)); return r;
}
__device__ __forceinline__ void upk2(ull v, float& lo, float& hi) {
    asm("mov.b64 {%0,%1}, %2;" : "=f"(lo), "=f"(hi) : "l"(v));
}
__device__ __forceinline__ ull fma2(ull a, ull b, ull c) {
    ull d; asm("fma.rn.f32x2 %0, %1, %2, %3;" : "=l"(d) : "l"(a), "l"(b), "l"(c)); return d;
}

__device__ __forceinline__ void grid_sync_c(int i) {
    volatile unsigned* ctr = (volatile unsigned*)&g_sync[i];
    __syncthreads();
    if (threadIdx.x == 0) {
        __threadfence();
        atomicAdd(&g_sync[i], 1u);
        while (*ctr < GRID) { __nanosleep(32); }
        __threadfence();
    }
    __syncthreads();
}

// ---------- smem plan (112KB/block, 2 blocks/SM) ----------
// P1: AB0 16KB @0 ; AB1 @16384 ; XG [2grp][2buf][64][16] 16KB @32768
// epi alias: Ep [16][512] 32KB @0 ; Ef [32][32] @32768 ; Qsp @36864 ; red @40960
// Xs2 [512][32] 64KB @49152 (cp.async)
// P3/P4 alias @0
#define OFF_AB0 0
#define OFF_AB1 16384
#define OFF_XG  32768
#define OFF_EP  0
#define OFF_EF  32768
#define OFF_QS  36864
#define OFF_RED 40960
#define OFF_XS2 49152
#define SMEM_TOTAL 114688

__global__ __launch_bounds__(NTHR, 2) void fused_kernel(const float* __restrict__ X,
                                                        const float* __restrict__ cw,
                                                        const float* __restrict__ scale,
                                                        float* __restrict__ out) {
    extern __shared__ unsigned char sm[];
    const int tid  = threadIdx.x;
    const int lane = tid & 31;
    const int w    = tid >> 5;           // 0..15
    const int grp  = w >> 3;             // 0/1
    const int wd   = w & 7;
    const int bid  = blockIdx.x;

    uint32_t smem_u32;
    asm("{ .reg .u64 t; cvta.to.shared.u64 t, %1; cvt.u32.u64 %0, t; }"
        : "=r"(smem_u32) : "l"(sm));

    // ============ P0: coefficients + C[k] ============
    if (bid == 0 && tid == 0) atomicExch(&g_sync[2], 0u);  // replay-safe pre-reset
    if (tid < 64) {
        int idx = bid*64 + tid;          // d*32+k
        int d = idx >> 5, k = idx & 31;
        float s = scale[idx];
        float c = cw[k*DD + d];
        float s2 = s*s;
        g_ABi[idx] = make_float2(s2, -2.f*s2*c);
    }
    if (bid < KK) {
        float* red = (float*)sm;         // [512]
        const int k = bid;
        float s = scale[tid*KK + k];
        float c = cw[k*DD + tid];
        red[tid] = s*s*c*c;
        __syncthreads();
        #pragma unroll
        for (int off = 256; off > 0; off >>= 1) {
            if (tid < off) red[tid] += red[tid + off];
            __syncthreads();
        }
        if (tid == 0) g_C[k] = red[0];
    }
    grid_sync_c(0);

    const int n0 = bid * 32;
    const int b  = bid >> 7;
    const float* Xb = X + (size_t)b*DD*NN + (n0 & (NN - 1));

    // ============ P1: E-GEMM, cp.async double-buffered ============
    ull acc[8];
    {
        // prologue: stage chunk 0 (AB 16KB + X 8KB)
        {
            #pragma unroll
            for (int it = 0; it < 2; it++) {
                int idx = tid + it*512;
                uint32_t dst = smem_u32 + OFF_AB0 + (uint32_t)idx*16u;
                const char* src = (const char*)g_ABi + idx*16;
                asm volatile("cp.async.ca.shared.global [%0], [%1], 16;" :: "r"(dst), "l"(src));
            }
            int g2 = tid >> 8, row = (tid >> 2) & 63, quad = tid & 3;
            uint32_t dst = smem_u32 + OFF_XG + (uint32_t)(g2*8192 + (row*16 + quad*4)*4);
            const float* src = Xb + g2*16 + (size_t)row*NN + quad*4;
            asm volatile("cp.async.ca.shared.global [%0], [%1], 16;" :: "r"(dst), "l"(src));
            asm volatile("cp.async.commit_group;");
        }
        #pragma unroll
        for (int i = 0; i < 8; i++) acc[i] = 0ull;

        #pragma unroll 1
        for (int c = 0; c < 8; c++) {
            asm volatile("cp.async.wait_group 0;");
            __syncthreads();                 // chunk c visible; buf (c+1)&1 free
            if (c < 7) {                     // stage chunk c+1 (overlaps compute)
                int nb = (c + 1) & 1;
                #pragma unroll
                for (int it = 0; it < 2; it++) {
                    int idx = tid + it*512;
                    uint32_t dst = smem_u32 + (nb ? OFF_AB1 : OFF_AB0) + (uint32_t)idx*16u;
                    const char* src = (const char*)g_ABi + (c+1)*16384 + idx*16;
                    asm volatile("cp.async.ca.shared.global [%0], [%1], 16;" :: "r"(dst), "l"(src));
                }
                int g2 = tid >> 8, row = (tid >> 2) & 63, quad = tid & 3;
                uint32_t dst = smem_u32 + OFF_XG +
                               (uint32_t)(g2*8192 + nb*4096 + (row*16 + quad*4)*4);
                const float* src = Xb + g2*16 + (size_t)((c+1)*64 + row)*NN + quad*4;
                asm volatile("cp.async.ca.shared.global [%0], [%1], 16;" :: "r"(dst), "l"(src));
                asm volatile("cp.async.commit_group;");
            }
            const float2* ABc = (const float2*)(sm + ((c & 1) ? OFF_AB1 : OFF_AB0));
            const float*  Xsc = (const float*)(sm + OFF_XG + grp*8192 + (c & 1)*4096);
            #pragma unroll
            for (int it = 0; it < 8; it++) {
                int dd = wd + it*8;
                float2 ab = ABc[dd*KK + lane];
                ull a2 = pk2(ab.x, ab.x), b2 = pk2(ab.y, ab.y);
                const float* xr = &Xsc[dd*16];
                #pragma unroll
                for (int g = 0; g < 4; g++) {
                    longlong2 xv = *reinterpret_cast<const longlong2*>(xr + g*4);
                    ull x01 = (ull)xv.x, x23 = (ull)xv.y;
                    ull t0 = fma2(a2, x01, b2);
                    acc[2*g]   = fma2(x01, t0, acc[2*g]);
                    ull t1 = fma2(a2, x23, b2);
                    acc[2*g+1] = fma2(x23, t1, acc[2*g+1]);
                }
            }
            __syncthreads();                 // done reading buf c&1
        }
    }

    // ---- kick off Xs2 [512 d][32 n] cp.async (overlaps epilogue) ----
    {
        #pragma unroll
        for (int it = 0; it < 8; it++) {
            int idx = tid + it*512;          // 0..4095 float4
            int row = idx >> 3, quad = idx & 7;
            uint32_t dst = smem_u32 + OFF_XS2 + (uint32_t)(row*32 + quad*4)*4u;
            const float* src = Xb + (size_t)row*NN + quad*4;
            asm volatile("cp.async.ca.shared.global [%0], [%1], 16;" :: "r"(dst), "l"(src));
        }
        asm volatile("cp.async.commit_group;");
    }

    // ---- epilogue: cross-warp E reduce, softmax, Q out ----
    {
        float* Ep  = (float*)(sm + OFF_EP);      // [16][512]
        float* Ef  = (float*)(sm + OFF_EF);      // [32][32]
        ull*   Qsp = (ull*)(sm + OFF_QS);        // [16][32]
        float* red = (float*)(sm + OFF_RED);     // [16][33]

        #pragma unroll
        for (int i = 0; i < 8; i++) {
            float lo, hi; upk2(acc[i], lo, hi);
            Ep[w*512 + (2*i  )*KK + lane] = lo;
            Ep[w*512 + (2*i+1)*KK + lane] = hi;
        }
        __syncthreads();
        #pragma unroll
        for (int it = 0; it < 2; it++) {
            int idx = tid + it*512;              // n*32+k
            int n = idx >> 5, k = idx & 31;
            int gg = n >> 4, nl = n & 15;
            float s = 0.f;
            #pragma unroll
            for (int wdd = 0; wdd < 8; wdd++)
                s += Ep[(gg*8 + wdd)*512 + nl*KK + k];
            Ef[idx] = s;
        }
        __syncthreads();

        float* Qout = out + ZSIZE;
        const float Ck = g_C[lane];
        float qv[2];
        float s1loc = 0.f;
        #pragma unroll
        for (int i = 0; i < 2; i++) {
            int n = w*2 + i;
            float arg = -0.5f * (Ef[n*KK + lane] + Ck);
            float m = arg;
            #pragma unroll
            for (int off = 16; off; off >>= 1) m = fmaxf(m, __shfl_xor_sync(~0u, m, off));
            float ex = __expf(arg - m);
            float ssum = ex;
            #pragma unroll
            for (int off = 16; off; off >>= 1) ssum += __shfl_xor_sync(~0u, ssum, off);
            float q = ex / ssum;
            Qout[(size_t)(n0 + n)*KK + lane] = q;
            qv[i] = q;
            s1loc += q;
        }
        Qsp[w*32 + lane] = pk2(qv[0], qv[1]);
        red[w*33 + lane] = s1loc;
        __syncthreads();
        if (w == 0) {
            float s = 0.f;
            #pragma unroll
            for (int i = 0; i < 16; i++) s += red[i*33 + lane];
            g_S1part[bid*KK + lane] = s;
        }
    }
    asm volatile("cp.async.wait_group 0;");
    __syncthreads();

    // ============ P2': M over 32 n, all 512 d (2 passes of 256 d) ============
    {
        const float* Xs2 = (const float*)(sm + OFF_XS2);   // [512][32]
        const ull*   Qsp = (const ull*)(sm + OFF_QS);
        const int chunk = bid & 127;
        float* dstc = g_M2 + (size_t)(b*128 + chunk)*DD*KK;

        #pragma unroll 1
        for (int pass = 0; pass < 2; pass++) {
            const int dbase = pass*256 + w*16;
            ull acc2[16];
            #pragma unroll
            for (int i = 0; i < 16; i++) acc2[i] = 0ull;
            #pragma unroll 1
            for (int ng = 0; ng < 2; ng++) {
                ull q2[8];
                #pragma unroll
                for (int j = 0; j < 8; j++)
                    q2[j] = Qsp[(ng*8 + j)*32 + lane];
                #pragma unroll
                for (int dl = 0; dl < 16; dl++) {
                    const float* xr = &Xs2[(dbase + dl)*32 + ng*16];
                    longlong2 xa = *(const longlong2*)(xr);
                    longlong2 xb = *(const longlong2*)(xr + 4);
                    longlong2 xc = *(const longlong2*)(xr + 8);
                    longlong2 xd = *(const longlong2*)(xr + 12);
                    ull a = acc2[dl];
                    a = fma2(q2[0], (ull)xa.x, a);
                    a = fma2(q2[1], (ull)xa.y, a);
                    a = fma2(q2[2], (ull)xb.x, a);
                    a = fma2(q2[3], (ull)xb.y, a);
                    a = fma2(q2[4], (ull)xc.x, a);
                    a = fma2(q2[5], (ull)xc.y, a);
                    a = fma2(q2[6], (ull)xd.x, a);
                    a = fma2(q2[7], (ull)xd.y, a);
                    acc2[dl] = a;
                }
            }
            #pragma unroll
            for (int dl = 0; dl < 16; dl++) {
                float lo, hi; upk2(acc2[dl], lo, hi);
                dstc[(dbase + dl)*KK + lane] = lo + hi;
            }
        }
    }
    grid_sync_c(1);
    if (bid == 0 && tid == 0) atomicExch(&g_sync[0], 0u);

    // ============ P3: S1, M reduce (128 chunks), Z, sumsq ============
    const int bf  = bid >> 7;
    const int dtf = bid & 127;
    const int d0f = dtf*4;
    const int wd4 = w & 3, cg = w >> 2;
    const int dfw = d0f + wd4;
    const size_t mi = ((size_t)bf*DD + dfw)*KK + lane;
    {
        float* redM = (float*)sm;            // [16][33]
        float* redS = (float*)(sm + 2176);   // [16][33]
        float* cwf  = (float*)(sm + 4352);   // [32][5]
        float* bsh  = (float*)(sm + 5120);   // [32]

        if (tid < 128) {
            int k = tid >> 2, dl = tid & 3;
            cwf[k*5 + dl] = cw[k*DD + d0f + dl];
        }
        // M partial: warp (cg,wd4) sums 32 chunks for d = dfw
        float mp = 0.f;
        const float* msrc = g_M2 + ((size_t)(bf*128 + cg*32)*DD + dfw)*KK + lane;
        #pragma unroll
        for (int j = 0; j < 32; j++)
            mp += msrc[(size_t)j*DD*KK];
        redM[w*33 + lane] = mp;

        // S1: 128 partials, warp sums 8
        float s1p = 0.f;
        #pragma unroll
        for (int j = 0; j < 8; j++)
            s1p += g_S1part[(bf*128 + w + 16*j)*KK + lane];
        redS[w*33 + lane] = s1p;
        __syncthreads();
        if (w == 0) {
            float s = 0.f;
            #pragma unroll
            for (int i = 0; i < 16; i++) s += redS[i*33 + lane];
            bsh[lane] = 1.f / s;
        }
        __syncthreads();
        float z = 0.f;
        if (w < 4) {
            float m = redM[w*33 + lane] + redM[(4+w)*33 + lane]
                    + redM[(8+w)*33 + lane] + redM[(12+w)*33 + lane];
            z = scale[dfw*KK + lane] * (m*bsh[lane] - cwf[lane*5 + wd4]);
            out[mi] = z;
        }
        __syncthreads();
        if (w < 4) redM[w*33 + lane] = z*z;
        __syncthreads();
        if (w == 0) {
            float s = 0.f;
            #pragma unroll
            for (int i = 0; i < 4; i++) s += redM[i*33 + lane];
            g_SS[(bf*128 + dtf)*KK + lane] = s;
        }
    }
    grid_sync_c(2);
    if (bid == 0 && tid == 0) atomicExch(&g_sync[1], 0u);

    // ============ P4: rescale ============
    {
        float* red = (float*)sm;
        float* bsh = (float*)(sm + 5120);
        float ssp = 0.f;
        #pragma unroll
        for (int j = 0; j < 8; j++)
            ssp += g_SS[(bf*128 + w + 16*j)*KK + lane];
        red[w*33 + lane] = ssp;
        __syncthreads();
        if (w == 0) {
            float s = 0.f;
            #pragma unroll
            for (int i = 0; i < 16; i++) s += red[i*33 + lane];
            bsh[lane] = rsqrtf(s);
        }
        __syncthreads();
        if (w < 4) out[mi] *= bsh[lane];
    }
}

extern "C" void kernel_launch(void* const* d_in, const int* in_sizes, int n_in,
                              void* d_out, int out_size) {
    const float* X     = (const float*)d_in[0];
    const float* cw    = (const float*)d_in[1];
    const float* scale = (const float*)d_in[2];
    float* out = (float*)d_out;

    cudaFuncSetAttribute(fused_kernel, cudaFuncAttributeMaxDynamicSharedMemorySize,
                         SMEM_TOTAL);
    fused_kernel<<<GRID, NTHR, SMEM_TOTAL>>>(X, cw, scale, out);
}